// round 16
// baseline (speedup 1.0000x reference)
#include <cuda_runtime.h>
#include <cstdint>

// 2-bit quantized embedding gather — R16: final policy A/B, __stwt
// (write-through) vs __stcs on the locked R8 body.
// input_ids: [262144] int32 ; bit_arr: [3.2M] int32 ; codebook: [4] fp32
// out: [262144, 128] fp32.
//
// Rationale: output is write-once/never-read. __stcs still allocates dirty
// L2 lines that must later drain (each line transits LTS twice); __stwt
// pushes sectors through at store time with no dirty-line lifecycle. Last
// untested cache-policy cell; everything else in the A/B matrix (MLP 4/8/16,
// TMA bulk store, default evict, persistent shell, 128/256-thr CTAs) is
// falsified at the 23.3-24.8us equilibrium.

#define TOK_PER_WARP 8

__global__ __launch_bounds__(256)
void embed2bit_kernel(const int4* __restrict__ ids4,
                      const unsigned int* __restrict__ bits,
                      const float* __restrict__ cb,
                      float4* __restrict__ out,
                      int n_tokens)
{
    int warp = (blockIdx.x * blockDim.x + threadIdx.x) >> 5;
    int lane = threadIdx.x & 31;

    int tok_base = warp * TOK_PER_WARP;
    if (tok_base >= n_tokens) return;

    // Two independent warp-uniform 16B loads = 8 token ids (broadcast).
    int4 ta = __ldg(&ids4[warp * 2 + 0]);
    int4 tb = __ldg(&ids4[warp * 2 + 1]);
    unsigned int tok[TOK_PER_WARP] = {
        (unsigned int)ta.x, (unsigned int)ta.y,
        (unsigned int)ta.z, (unsigned int)ta.w,
        (unsigned int)tb.x, (unsigned int)tb.y,
        (unsigned int)tb.z, (unsigned int)tb.w };

    // 8 independent code-block loads in flight (MLP=8). 4 lanes share a word.
    unsigned int w[TOK_PER_WARP];
    #pragma unroll
    for (int j = 0; j < TOK_PER_WARP; j++)
        w[j] = __ldg(&bits[(size_t)tok[j] * 8 + (lane >> 2)]);

    // Codebook in registers; decode via predicated selects, no memory LUT.
    float c0 = __ldg(&cb[0]);
    float c1 = __ldg(&cb[1]);
    float c2 = __ldg(&cb[2]);
    float c3 = __ldg(&cb[3]);

    #define DECODE(c) (((c) & 1u) ? (((c) & 2u) ? c3 : c1) \
                                  : (((c) & 2u) ? c2 : c0))
    unsigned int sel = lane & 3;   // which byte of the word this lane owns
    float4* obase = out + (size_t)tok_base * 32 + lane;

    #pragma unroll
    for (int j = 0; j < TOK_PER_WARP; j++) {
        unsigned int byte = __byte_perm(w[j], 0u, sel) & 0xFFu;  // 1 PRMT
        float4 v;
        v.x = DECODE(((byte >> 0) & 3u));
        v.y = DECODE(((byte >> 2) & 3u));
        v.z = DECODE(((byte >> 4) & 3u));
        v.w = DECODE(((byte >> 6) & 3u));
        // 512 B fully-coalesced WRITE-THROUGH store: no dirty-L2 lifecycle.
        __stwt(obase + j * 32, v);
    }
    #undef DECODE
}

extern "C" void kernel_launch(void* const* d_in, const int* in_sizes, int n_in,
                              void* d_out, int out_size)
{
    const int4*         ids4 = (const int4*)d_in[0];
    const unsigned int* bits = (const unsigned int*)d_in[1];
    const float*        cb   = (const float*)d_in[2];
    float4*             out  = (float4*)d_out;

    int n_tokens = in_sizes[0];                       // 262144 (divisible by 8)
    int warps = (n_tokens + TOK_PER_WARP - 1) / TOK_PER_WARP;
    int threads = 256;                                // 8 warps/block
    int blocks = (warps + 7) / 8;                     // 4096

    embed2bit_kernel<<<blocks, threads>>>(ids4, bits, cb, out, n_tokens);
}

// round 17
// speedup vs baseline: 1.1764x; 1.1764x over previous
#include <cuda_runtime.h>
#include <cstdint>

// 2-bit quantized embedding gather — FINAL (R8 configuration, locked).
// input_ids: [262144] int32 ; bit_arr: [3.2M] int32 ; codebook: [4] fp32
// out: [262144, 128] fp32.
//
// Structure: pos = token*128 + dim, bitpos = pos*2 -> each token's 128 codes
// are an aligned 8-word (32B) block at word token*8. Lane t handles dims
// 4t..4t+3 = byte t of that block: one LDG.32 per token per lane, one
// STG.128 per token per lane (512B fully-coalesced per warp).
//
// Complete A/B matrix (all falsified at the ~23.4us kernel equilibrium):
//   MLP 1/4/8/16 ................ 39.5 / 33.5 / 23.4 / 23.9 us
//   SMEM + cp.async.bulk store .. 24.0us   (store-issue path not the wall)
//   __stcs / default / __stwt ... 23.4 / 24.4 / 23.8us (policy-independent)
//   persistent one-wave shell ... 24.8us   (wave structure not the wall)
//   128-thread CTAs ............. 23.3us   (neutral)
// Floor: 134MB mandatory fp32 output in 23.4us = 5.75 TB/s pure write
// traffic = HBM3e write-path ceiling. Bytes are irreducible.

#define TOK_PER_WARP 8

__global__ __launch_bounds__(256)
void embed2bit_kernel(const int4* __restrict__ ids4,
                      const unsigned int* __restrict__ bits,
                      const float* __restrict__ cb,
                      float4* __restrict__ out,
                      int n_tokens)
{
    int warp = (blockIdx.x * blockDim.x + threadIdx.x) >> 5;
    int lane = threadIdx.x & 31;

    int tok_base = warp * TOK_PER_WARP;
    if (tok_base >= n_tokens) return;

    // Two independent warp-uniform 16B loads = 8 token ids (broadcast).
    int4 ta = __ldg(&ids4[warp * 2 + 0]);
    int4 tb = __ldg(&ids4[warp * 2 + 1]);
    unsigned int tok[TOK_PER_WARP] = {
        (unsigned int)ta.x, (unsigned int)ta.y,
        (unsigned int)ta.z, (unsigned int)ta.w,
        (unsigned int)tb.x, (unsigned int)tb.y,
        (unsigned int)tb.z, (unsigned int)tb.w };

    // 8 independent code-block loads in flight (MLP=8). 4 lanes share a word.
    unsigned int w[TOK_PER_WARP];
    #pragma unroll
    for (int j = 0; j < TOK_PER_WARP; j++)
        w[j] = __ldg(&bits[(size_t)tok[j] * 8 + (lane >> 2)]);

    // Codebook in registers; decode via predicated selects, no memory LUT.
    float c0 = __ldg(&cb[0]);
    float c1 = __ldg(&cb[1]);
    float c2 = __ldg(&cb[2]);
    float c3 = __ldg(&cb[3]);

    #define DECODE(c) (((c) & 1u) ? (((c) & 2u) ? c3 : c1) \
                                  : (((c) & 2u) ? c2 : c0))
    unsigned int sel = lane & 3;   // which byte of the word this lane owns
    float4* obase = out + (size_t)tok_base * 32 + lane;

    #pragma unroll
    for (int j = 0; j < TOK_PER_WARP; j++) {
        unsigned int byte = __byte_perm(w[j], 0u, sel) & 0xFFu;  // 1 PRMT
        float4 v;
        v.x = DECODE(((byte >> 0) & 3u));
        v.y = DECODE(((byte >> 2) & 3u));
        v.z = DECODE(((byte >> 4) & 3u));
        v.w = DECODE(((byte >> 6) & 3u));
        // 512 B fully-coalesced streaming store (write-once: evict-first).
        __stcs(obase + j * 32, v);
    }
    #undef DECODE
}

extern "C" void kernel_launch(void* const* d_in, const int* in_sizes, int n_in,
                              void* d_out, int out_size)
{
    const int4*         ids4 = (const int4*)d_in[0];
    const unsigned int* bits = (const unsigned int*)d_in[1];
    const float*        cb   = (const float*)d_in[2];
    float4*             out  = (float4*)d_out;

    int n_tokens = in_sizes[0];                       // 262144 (divisible by 8)
    int warps = (n_tokens + TOK_PER_WARP - 1) / TOK_PER_WARP;
    int threads = 256;                                // 8 warps/block
    int blocks = (warps + 7) / 8;                     // 4096

    embed2bit_kernel<<<blocks, threads>>>(ids4, bits, cb, out, n_tokens);
}